// round 3
// baseline (speedup 1.0000x reference)
#include <cuda_runtime.h>
#include <math.h>
#include <stdint.h>

// ---------------- problem constants ----------------
#define BB    32
#define TT    720
#define CC    862
#define MM    4
#define LTOK  866
#define DMOD  512
#define HH    8
#define EH    64
#define FFD   2048
#define PRED  720
#define NROW  (BB * LTOK)    // 27712
#define LAYERS 3

// ---------------- device scratch ----------------
__device__ float g_tok [BB * LTOK * TT];
__device__ float g_x   [NROW * DMOD];
__device__ float g_q   [NROW * DMOD];
__device__ float g_k   [NROW * DMOD];
__device__ float g_v   [NROW * DMOD];
__device__ float g_a   [NROW * DMOD];
__device__ float g_tmp [NROW * DMOD];
__device__ float g_ff  [NROW * FFD];
__device__ float g_proj[NROW * PRED];
__device__ float g_mean[BB * CC];
__device__ float g_std [BB * CC];
__device__ float g_rstd[BB * CC];

// ---------------- RevIN stats ----------------
__global__ void revin_stats_kernel(const float* __restrict__ xe,
                                   float* __restrict__ mean,
                                   float* __restrict__ stdv,
                                   float* __restrict__ rstd) {
    int c = blockIdx.x * 128 + threadIdx.x;
    int b = blockIdx.y;
    if (c >= CC) return;
    const float* p = xe + (size_t)b * TT * CC + c;
    float s = 0.f, q = 0.f;
    for (int t = 0; t < TT; t++) {
        float v = p[(size_t)t * CC];
        s += v; q += v * v;
    }
    float mu  = s * (1.0f / TT);
    float var = q * (1.0f / TT) - mu * mu;
    float sd  = sqrtf(var + 1e-5f);
    int i = b * CC + c;
    mean[i] = mu; stdv[i] = sd; rstd[i] = 1.0f / sd;
}

// ---------------- tok build ----------------
__global__ void build_tok_kernel(const float* __restrict__ xe,
                                 const float* __restrict__ xm,
                                 const float* __restrict__ mean,
                                 const float* __restrict__ rstd,
                                 const float* __restrict__ rw,
                                 const float* __restrict__ rb,
                                 float* __restrict__ tok) {
    int idx = blockIdx.x * blockDim.x + threadIdx.x;
    const int total = BB * LTOK * TT;
    if (idx >= total) return;
    int t = idx % TT;
    int l = (idx / TT) % LTOK;
    int b = idx / (TT * LTOK);
    float val;
    if (l < CC) {
        float xv = xe[((size_t)b * TT + t) * CC + l];
        int i = b * CC + l;
        val = (xv - mean[i]) * rstd[i] * rw[l] + rb[l];
    } else {
        val = xm[((size_t)b * TT + t) * MM + (l - CC)];
    }
    tok[idx] = val;
}

// ---------------- TF32 GEMM: 128x256x16, 8 warps of 64x64 ----------------
__device__ __forceinline__ uint32_t f2tf32(float x) {
    uint32_t r;
    asm("cvt.rna.tf32.f32 %0, %1;" : "=r"(r) : "f"(x));
    return r;
}

#define APAD 136   // 128 + 8
#define BPAD 264   // 256 + 8
#define ASZ  (16 * APAD)
#define BSZ  (16 * BPAD)

__global__ __launch_bounds__(256, 1)
void gemm_tf32_kernel(const float* __restrict__ A, const float* __restrict__ W,
                      const float* __restrict__ bias, float* __restrict__ Cm,
                      int N, int K, int Dout, int act) {
    extern __shared__ uint32_t smem[];
    uint32_t* As = smem;              // [2][16][APAD]
    uint32_t* Bs = smem + 2 * ASZ;    // [2][16][BPAD]

    const int tid  = threadIdx.x;
    const int lane = tid & 31;
    const int wid  = tid >> 5;
    const int wRow = (wid & 1) * 64;      // 2 warps along M
    const int wCol = (wid >> 1) * 64;     // 4 warps along N
    const int gID  = lane >> 2;
    const int tg   = lane & 3;

    const int row0 = blockIdx.y * 128;
    const int col0 = blockIdx.x * 256;

    // A staging: 2 float4 per thread
    const int aRow = tid >> 2;            // 0..63, +64
    const int aK   = (tid & 3) << 2;
    const int ar0  = min(row0 + aRow,      N - 1);
    const int ar1  = min(row0 + aRow + 64, N - 1);
    // B staging: 4 float4 per thread
    const int bK   = tid >> 6;            // 0..3  (+4,+8,+12)
    const int bCol = (tid & 63) << 2;     // 0..252
    const int bc   = min(col0 + bCol, Dout - 4);

    float acc[4][8][4];
#pragma unroll
    for (int i = 0; i < 4; i++)
#pragma unroll
        for (int j = 0; j < 8; j++)
#pragma unroll
            for (int r = 0; r < 4; r++) acc[i][j][r] = 0.f;

    const int nIter = K >> 4;

    float4 av0, av1, bv[4];
    // prologue loads
    av0 = *reinterpret_cast<const float4*>(A + (size_t)ar0 * K + aK);
    av1 = *reinterpret_cast<const float4*>(A + (size_t)ar1 * K + aK);
#pragma unroll
    for (int j = 0; j < 4; j++)
        bv[j] = *reinterpret_cast<const float4*>(W + (size_t)(bK + 4 * j) * Dout + bc);

#define STAGE(bufp)                                                              \
    {                                                                            \
        uint32_t* Ab = As + (bufp) * ASZ;                                        \
        uint32_t* Bb = Bs + (bufp) * BSZ;                                        \
        Ab[(aK + 0) * APAD + aRow] = f2tf32(av0.x);                              \
        Ab[(aK + 1) * APAD + aRow] = f2tf32(av0.y);                              \
        Ab[(aK + 2) * APAD + aRow] = f2tf32(av0.z);                              \
        Ab[(aK + 3) * APAD + aRow] = f2tf32(av0.w);                              \
        Ab[(aK + 0) * APAD + aRow + 64] = f2tf32(av1.x);                         \
        Ab[(aK + 1) * APAD + aRow + 64] = f2tf32(av1.y);                         \
        Ab[(aK + 2) * APAD + aRow + 64] = f2tf32(av1.z);                         \
        Ab[(aK + 3) * APAD + aRow + 64] = f2tf32(av1.w);                         \
        _Pragma("unroll")                                                        \
        for (int j = 0; j < 4; j++) {                                            \
            uint4 pk;                                                            \
            pk.x = f2tf32(bv[j].x); pk.y = f2tf32(bv[j].y);                      \
            pk.z = f2tf32(bv[j].z); pk.w = f2tf32(bv[j].w);                      \
            *reinterpret_cast<uint4*>(&Bb[(bK + 4 * j) * BPAD + bCol]) = pk;     \
        }                                                                        \
    }

    STAGE(0)
    __syncthreads();

    int buf = 0;
    for (int t = 0; t < nIter; t++) {
        if (t + 1 < nIter) {
            int k0 = (t + 1) << 4;
            av0 = *reinterpret_cast<const float4*>(A + (size_t)ar0 * K + k0 + aK);
            av1 = *reinterpret_cast<const float4*>(A + (size_t)ar1 * K + k0 + aK);
#pragma unroll
            for (int j = 0; j < 4; j++)
                bv[j] = *reinterpret_cast<const float4*>(W + (size_t)(k0 + bK + 4 * j) * Dout + bc);
        }
        const uint32_t* Ab = As + buf * ASZ;
        const uint32_t* Bb = Bs + buf * BSZ;
#pragma unroll
        for (int ks = 0; ks < 2; ks++) {
            const int kb = ks * 8;
            uint32_t af[4][4];
            uint32_t bf[8][2];
#pragma unroll
            for (int i = 0; i < 4; i++) {
                int r = wRow + i * 16 + gID;
                af[i][0] = Ab[(kb + tg) * APAD + r];
                af[i][1] = Ab[(kb + tg) * APAD + r + 8];
                af[i][2] = Ab[(kb + tg + 4) * APAD + r];
                af[i][3] = Ab[(kb + tg + 4) * APAD + r + 8];
            }
#pragma unroll
            for (int j = 0; j < 8; j++) {
                int c = wCol + j * 8 + gID;
                bf[j][0] = Bb[(kb + tg) * BPAD + c];
                bf[j][1] = Bb[(kb + tg + 4) * BPAD + c];
            }
#pragma unroll
            for (int i = 0; i < 4; i++)
#pragma unroll
                for (int j = 0; j < 8; j++) {
                    asm volatile(
                        "mma.sync.aligned.m16n8k8.row.col.f32.tf32.tf32.f32 "
                        "{%0,%1,%2,%3}, {%4,%5,%6,%7}, {%8,%9}, {%0,%1,%2,%3};"
                        : "+f"(acc[i][j][0]), "+f"(acc[i][j][1]),
                          "+f"(acc[i][j][2]), "+f"(acc[i][j][3])
                        : "r"(af[i][0]), "r"(af[i][1]), "r"(af[i][2]), "r"(af[i][3]),
                          "r"(bf[j][0]), "r"(bf[j][1]));
                }
        }
        if (t + 1 < nIter) {
            int nb = buf ^ 1;
            __syncthreads();
            STAGE(nb)
            __syncthreads();
            buf = nb;
        }
    }

    // epilogue
#pragma unroll
    for (int i = 0; i < 4; i++) {
#pragma unroll
        for (int half = 0; half < 2; half++) {
            int r = row0 + wRow + i * 16 + gID + half * 8;
            if (r >= N) continue;
#pragma unroll
            for (int j = 0; j < 8; j++) {
                int col = col0 + wCol + j * 8 + tg * 2;
                if (col >= Dout) continue;
                float v0 = acc[i][j][half * 2 + 0] + bias[col];
                float v1 = acc[i][j][half * 2 + 1] + bias[col + 1];
                if (act == 1) {
                    v0 = 1.0f / (1.0f + expf(-v0));
                    v1 = 1.0f / (1.0f + expf(-v1));
                } else if (act == 2) {
                    v0 = 0.5f * v0 * (1.0f + erff(v0 * 0.70710678118654752f));
                    v1 = 0.5f * v1 * (1.0f + erff(v1 * 0.70710678118654752f));
                }
                *reinterpret_cast<float2*>(Cm + (size_t)r * Dout + col) =
                    make_float2(v0, v1);
            }
        }
    }
}
#undef STAGE

// ---------------- flow attention ----------------
__global__ __launch_bounds__(256)
void attn_kernel(const float* __restrict__ q, const float* __restrict__ k,
                 const float* __restrict__ v, float* __restrict__ out) {
    int b = blockIdx.x >> 3, h = blockIdx.x & 7;
    const float* qp = q + ((size_t)b * LTOK) * DMOD + h * EH;
    const float* kp = k + ((size_t)b * LTOK) * DMOD + h * EH;
    const float* vp = v + ((size_t)b * LTOK) * DMOD + h * EH;
    float*       op = out + ((size_t)b * LTOK) * DMOD + h * EH;
    int tid = threadIdx.x, lane = tid & 31, wid = tid >> 5;
    const float eps = 1e-6f;

    __shared__ float s_nr[LTOK], s_nc[LTOK], s_nrref[LTOK], s_ncref[LTOK];
    __shared__ float s_ksum[EH], s_qsum[EH], s_kns[EH], s_qns[EH];
    __shared__ float s_kv[EH][EH];
    __shared__ float s_ck[8][EH], s_cv[8][EH];
    __shared__ float s_red[8];

    {
        int e = tid & 63, part = tid >> 6;
        float ka = 0.f, qa = 0.f;
        for (int s = part; s < LTOK; s += 4) {
            ka += kp[(size_t)s * DMOD + e];
            qa += qp[(size_t)s * DMOD + e];
        }
        s_ck[part][e] = ka;
        s_cv[part][e] = qa;
    }
    __syncthreads();
    if (tid < EH) {
        s_ksum[tid] = s_ck[0][tid] + s_ck[1][tid] + s_ck[2][tid] + s_ck[3][tid];
        s_qsum[tid] = s_cv[0][tid] + s_cv[1][tid] + s_cv[2][tid] + s_cv[3][tid];
    }
    __syncthreads();

    for (int r = wid; r < LTOK; r += 8) {
        float qv0 = qp[(size_t)r * DMOD + lane], qv1 = qp[(size_t)r * DMOD + lane + 32];
        float kv0 = kp[(size_t)r * DMOD + lane], kv1 = kp[(size_t)r * DMOD + lane + 32];
        float dq = (qv0 + eps) * (s_ksum[lane] + eps) + (qv1 + eps) * (s_ksum[lane + 32] + eps);
        float dk = (kv0 + eps) * (s_qsum[lane] + eps) + (kv1 + eps) * (s_qsum[lane + 32] + eps);
        for (int o = 16; o; o >>= 1) {
            dq += __shfl_xor_sync(0xffffffffu, dq, o);
            dk += __shfl_xor_sync(0xffffffffu, dk, o);
        }
        if (lane == 0) { s_nr[r] = 1.0f / dq; s_nc[r] = 1.0f / dk; }
    }
    __syncthreads();

    {
        int e = tid & 63, part = tid >> 6;
        float ka = 0.f, qa = 0.f;
        for (int s = part; s < LTOK; s += 4) {
            ka += kp[(size_t)s * DMOD + e] * s_nc[s];
            qa += qp[(size_t)s * DMOD + e] * s_nr[s];
        }
        s_ck[part][e] = ka;
        s_cv[part][e] = qa;
    }
    __syncthreads();
    if (tid < EH) {
        s_kns[tid] = s_ck[0][tid] + s_ck[1][tid] + s_ck[2][tid] + s_ck[3][tid];
        s_qns[tid] = s_cv[0][tid] + s_cv[1][tid] + s_cv[2][tid] + s_cv[3][tid];
    }
    __syncthreads();

    for (int r = wid; r < LTOK; r += 8) {
        float qv0 = qp[(size_t)r * DMOD + lane], qv1 = qp[(size_t)r * DMOD + lane + 32];
        float kv0 = kp[(size_t)r * DMOD + lane], kv1 = kp[(size_t)r * DMOD + lane + 32];
        float dq = (qv0 + eps) * (s_kns[lane] + eps) + (qv1 + eps) * (s_kns[lane + 32] + eps);
        float dk = (kv0 + eps) * (s_qns[lane] + eps) + (kv1 + eps) * (s_qns[lane + 32] + eps);
        for (int o = 16; o; o >>= 1) {
            dq += __shfl_xor_sync(0xffffffffu, dq, o);
            dk += __shfl_xor_sync(0xffffffffu, dk, o);
        }
        if (lane == 0) {
            s_nrref[r] = 1.0f / (1.0f + expf(-dq));
            s_ncref[r] = dk;
        }
    }
    __syncthreads();

    float lmax = -1e30f;
    for (int s = tid; s < LTOK; s += 256) lmax = fmaxf(lmax, s_ncref[s]);
    for (int o = 16; o; o >>= 1) lmax = fmaxf(lmax, __shfl_xor_sync(0xffffffffu, lmax, o));
    if (lane == 0) s_red[wid] = lmax;
    __syncthreads();
    if (tid == 0) {
        float m = s_red[0];
        for (int i = 1; i < 8; i++) m = fmaxf(m, s_red[i]);
        s_red[0] = m;
    }
    __syncthreads();
    lmax = s_red[0];
    __syncthreads();
    float lsum = 0.f;
    for (int s = tid; s < LTOK; s += 256) {
        float ev = expf(s_ncref[s] - lmax);
        s_ncref[s] = ev;
        lsum += ev;
    }
    for (int o = 16; o; o >>= 1) lsum += __shfl_xor_sync(0xffffffffu, lsum, o);
    if (lane == 0) s_red[wid] = lsum;
    __syncthreads();
    if (tid == 0) {
        float m = 0.f;
        for (int i = 0; i < 8; i++) m += s_red[i];
        s_red[0] = m;
    }
    __syncthreads();
    float scl = (float)LTOK / s_red[0];
    __syncthreads();
    for (int s = tid; s < LTOK; s += 256) s_ncref[s] *= scl;
    __syncthreads();

    int e_own = tid >> 2;
    int d0    = (tid & 3) * 16;
    float acc[16];
#pragma unroll
    for (int i = 0; i < 16; i++) acc[i] = 0.f;
    for (int s0 = 0; s0 < LTOK; s0 += 8) {
        for (int i = tid; i < 512; i += 256) {
            int j = i >> 6, e = i & 63;
            int s = s0 + j;
            float kk = 0.f, vv = 0.f;
            if (s < LTOK) {
                kk = kp[(size_t)s * DMOD + e];
                vv = vp[(size_t)s * DMOD + e] * s_ncref[s];
            }
            s_ck[j][e] = kk;
            s_cv[j][e] = vv;
        }
        __syncthreads();
#pragma unroll
        for (int j = 0; j < 8; j++) {
            float ke = s_ck[j][e_own];
#pragma unroll
            for (int i = 0; i < 16; i++) acc[i] += ke * s_cv[j][d0 + i];
        }
        __syncthreads();
    }
#pragma unroll
    for (int i = 0; i < 16; i++) s_kv[e_own][d0 + i] = acc[i];
    __syncthreads();

    for (int r = wid; r < LTOK; r += 8) {
        s_ck[wid][lane]      = qp[(size_t)r * DMOD + lane];
        s_ck[wid][lane + 32] = qp[(size_t)r * DMOD + lane + 32];
        __syncwarp();
        float a0 = 0.f, a1 = 0.f;
#pragma unroll
        for (int e = 0; e < EH; e++) {
            float qv = s_ck[wid][e];
            a0 += qv * s_kv[e][lane];
            a1 += qv * s_kv[e][lane + 32];
        }
        float sc = s_nr[r] * s_nrref[r];
        op[(size_t)r * DMOD + lane]      = a0 * sc;
        op[(size_t)r * DMOD + lane + 32] = a1 * sc;
        __syncwarp();
    }
}

// ---------------- residual add + LayerNorm ----------------
__global__ __launch_bounds__(256)
void add_ln_kernel(float* __restrict__ x, const float* __restrict__ res,
                   const float* __restrict__ w, const float* __restrict__ bb,
                   int useRes) {
    __shared__ float s_s[8], s_q[8];
    int row = blockIdx.x, tid = threadIdx.x, lane = tid & 31, wid = tid >> 5;
    size_t base = (size_t)row * DMOD;
    float v0 = x[base + tid], v1 = x[base + tid + 256];
    if (useRes) { v0 += res[base + tid]; v1 += res[base + tid + 256]; }
    float s = v0 + v1, q = v0 * v0 + v1 * v1;
    for (int o = 16; o; o >>= 1) {
        s += __shfl_xor_sync(0xffffffffu, s, o);
        q += __shfl_xor_sync(0xffffffffu, q, o);
    }
    if (lane == 0) { s_s[wid] = s; s_q[wid] = q; }
    __syncthreads();
    if (tid == 0) {
        float ss = 0.f, qq = 0.f;
        for (int i = 0; i < 8; i++) { ss += s_s[i]; qq += s_q[i]; }
        s_s[0] = ss; s_q[0] = qq;
    }
    __syncthreads();
    float mu  = s_s[0] * (1.0f / DMOD);
    float var = s_q[0] * (1.0f / DMOD) - mu * mu;
    float r   = rsqrtf(var + 1e-5f);
    x[base + tid]       = (v0 - mu) * r * w[tid] + bb[tid];
    x[base + tid + 256] = (v1 - mu) * r * w[tid + 256] + bb[tid + 256];
}

// ---------------- output: transpose + RevIN denorm ----------------
__global__ void out_kernel(const float* __restrict__ proj,
                           const float* __restrict__ rw, const float* __restrict__ rb,
                           const float* __restrict__ mean, const float* __restrict__ stdv,
                           float* __restrict__ out) {
    int idx = blockIdx.x * blockDim.x + threadIdx.x;
    const int total = BB * PRED * CC;
    if (idx >= total) return;
    int c = idx % CC;
    int t = (idx / CC) % PRED;
    int b = idx / (CC * PRED);
    float p = proj[((size_t)b * LTOK + c) * PRED + t];
    float v = (p - rb[c]) / (rw[c] + 1e-10f);
    out[idx] = v * stdv[b * CC + c] + mean[b * CC + c];
}

// ---------------- host orchestration ----------------
#define GEMM_SMEM (2 * (ASZ + BSZ) * 4)

static inline void launch_gemm(const float* A, const float* W, const float* bias,
                               float* Cm, int N, int K, int Dout, int act) {
    dim3 grid((Dout + 255) / 256, (N + 127) / 128);
    gemm_tf32_kernel<<<grid, 256, GEMM_SMEM>>>(A, W, bias, Cm, N, K, Dout, act);
}

extern "C" void kernel_launch(void* const* d_in, const int* in_sizes, int n_in,
                              void* d_out, int out_size) {
    const float* x_enc   = (const float*)d_in[0];
    const float* x_mark  = (const float*)d_in[1];
    const float* revin_w = (const float*)d_in[4];
    const float* revin_b = (const float*)d_in[5];
    const float* emb_W   = (const float*)d_in[6];
    const float* emb_b   = (const float*)d_in[7];
    const float* Wq = (const float*)d_in[8],  *bq = (const float*)d_in[9];
    const float* Wk = (const float*)d_in[10], *bk = (const float*)d_in[11];
    const float* Wv = (const float*)d_in[12], *bv = (const float*)d_in[13];
    const float* Wo = (const float*)d_in[14], *bo = (const float*)d_in[15];
    const float* ff1_W = (const float*)d_in[16], *ff1_b = (const float*)d_in[17];
    const float* ff2_W = (const float*)d_in[18], *ff2_b = (const float*)d_in[19];
    const float* ln1_w = (const float*)d_in[20], *ln1_b = (const float*)d_in[21];
    const float* ln2_w = (const float*)d_in[22], *ln2_b = (const float*)d_in[23];
    const float* lnf_w = (const float*)d_in[24], *lnf_b = (const float*)d_in[25];
    const float* proj_W = (const float*)d_in[26], *proj_b = (const float*)d_in[27];

    static int smem_set = 0;
    if (!smem_set) {
        cudaFuncSetAttribute(gemm_tf32_kernel,
                             cudaFuncAttributeMaxDynamicSharedMemorySize, GEMM_SMEM);
        smem_set = 1;
    }

    float *tok, *x, *q, *k, *v, *a, *tmp, *ff, *proj, *mean, *stdv, *rstd;
    cudaGetSymbolAddress((void**)&tok,  g_tok);
    cudaGetSymbolAddress((void**)&x,    g_x);
    cudaGetSymbolAddress((void**)&q,    g_q);
    cudaGetSymbolAddress((void**)&k,    g_k);
    cudaGetSymbolAddress((void**)&v,    g_v);
    cudaGetSymbolAddress((void**)&a,    g_a);
    cudaGetSymbolAddress((void**)&tmp,  g_tmp);
    cudaGetSymbolAddress((void**)&ff,   g_ff);
    cudaGetSymbolAddress((void**)&proj, g_proj);
    cudaGetSymbolAddress((void**)&mean, g_mean);
    cudaGetSymbolAddress((void**)&stdv, g_std);
    cudaGetSymbolAddress((void**)&rstd, g_rstd);

    revin_stats_kernel<<<dim3((CC + 127) / 128, BB), 128>>>(x_enc, mean, stdv, rstd);
    {
        int total = BB * LTOK * TT;
        build_tok_kernel<<<(total + 255) / 256, 256>>>(x_enc, x_mark, mean, rstd,
                                                       revin_w, revin_b, tok);
    }
    launch_gemm(tok, emb_W, emb_b, x, NROW, TT, DMOD, 0);

    for (int l = 0; l < LAYERS; l++) {
        const float* wq = Wq + (size_t)l * DMOD * DMOD;
        const float* wk = Wk + (size_t)l * DMOD * DMOD;
        const float* wv = Wv + (size_t)l * DMOD * DMOD;
        const float* wo = Wo + (size_t)l * DMOD * DMOD;
        launch_gemm(x, wq, bq + l * DMOD, q, NROW, DMOD, DMOD, 1);
        launch_gemm(x, wk, bk + l * DMOD, k, NROW, DMOD, DMOD, 1);
        launch_gemm(x, wv, bv + l * DMOD, v, NROW, DMOD, DMOD, 0);
        attn_kernel<<<BB * HH, 256>>>(q, k, v, a);
        launch_gemm(a, wo, bo + l * DMOD, tmp, NROW, DMOD, DMOD, 0);
        add_ln_kernel<<<NROW, 256>>>(x, tmp, ln1_w + l * DMOD, ln1_b + l * DMOD, 1);
        launch_gemm(x, ff1_W + (size_t)l * DMOD * FFD, ff1_b + l * FFD, ff,
                    NROW, DMOD, FFD, 2);
        launch_gemm(ff, ff2_W + (size_t)l * FFD * DMOD, ff2_b + l * DMOD, tmp,
                    NROW, FFD, DMOD, 0);
        add_ln_kernel<<<NROW, 256>>>(x, tmp, ln2_w + l * DMOD, ln2_b + l * DMOD, 1);
    }
    add_ln_kernel<<<NROW, 256>>>(x, nullptr, lnf_w, lnf_b, 0);
    launch_gemm(x, proj_W, proj_b, proj, NROW, DMOD, PRED, 0);
    {
        int total = BB * PRED * CC;
        out_kernel<<<(total + 255) / 256, 256>>>(proj, revin_w, revin_b, mean, stdv,
                                                 (float*)d_out);
    }
}

// round 4
// speedup vs baseline: 1.1916x; 1.1916x over previous
#include <cuda_runtime.h>
#include <math.h>
#include <stdint.h>

// ---------------- problem constants ----------------
#define BB    32
#define TT    720
#define CC    862
#define MM    4
#define LTOK  866
#define DMOD  512
#define HH    8
#define EH    64
#define FFD   2048
#define PRED  720
#define NROW  (BB * LTOK)        // 27712
#define NPAD  27776              // 217 * 128
#define LAYERS 3

// ---------------- device scratch ----------------
__device__ uint32_t g_tok [NPAD * TT];       // tf32 tokens [B*LTOK(pad), T]
__device__ float    g_x   [NROW * DMOD];
__device__ uint32_t g_xt  [NPAD * DMOD];     // tf32 copy of x
__device__ float    g_q   [NROW * DMOD];
__device__ float    g_k   [NROW * DMOD];
__device__ float    g_v   [NROW * DMOD];
__device__ uint32_t g_a   [NPAD * DMOD];     // attn out (tf32)
__device__ float    g_tmp [NROW * DMOD];
__device__ uint32_t g_ff  [NPAD * FFD];      // gelu out (tf32)
__device__ float    g_proj[NROW * PRED];
__device__ float    g_mean[BB * CC];
__device__ float    g_std [BB * CC];
__device__ float    g_rstd[BB * CC];
// tf32 weights
__device__ uint32_t g_wemb_t [TT * DMOD];
__device__ uint32_t g_wq_t   [LAYERS * DMOD * DMOD];
__device__ uint32_t g_wk_t   [LAYERS * DMOD * DMOD];
__device__ uint32_t g_wv_t   [LAYERS * DMOD * DMOD];
__device__ uint32_t g_wo_t   [LAYERS * DMOD * DMOD];
__device__ uint32_t g_wff1_t [LAYERS * DMOD * FFD];
__device__ uint32_t g_wff2_t [LAYERS * FFD * DMOD];
__device__ uint32_t g_wproj_t[DMOD * PRED];

__device__ __forceinline__ uint32_t f2tf32(float x) {
    uint32_t r;
    asm("cvt.rna.tf32.f32 %0, %1;" : "=r"(r) : "f"(x));
    return r;
}

// ---------------- fp32 -> tf32 convert ----------------
__global__ void cvt_kernel(const float* __restrict__ src, uint32_t* __restrict__ dst, int n) {
    int i = blockIdx.x * 256 + threadIdx.x;
    int stride = gridDim.x * 256;
    for (; i < n; i += stride) dst[i] = f2tf32(src[i]);
}

// ---------------- RevIN stats ----------------
__global__ void revin_stats_kernel(const float* __restrict__ xe,
                                   float* __restrict__ mean,
                                   float* __restrict__ stdv,
                                   float* __restrict__ rstd) {
    int c = blockIdx.x * 128 + threadIdx.x;
    int b = blockIdx.y;
    if (c >= CC) return;
    const float* p = xe + (size_t)b * TT * CC + c;
    float s = 0.f, q = 0.f;
    for (int t = 0; t < TT; t++) {
        float v = p[(size_t)t * CC];
        s += v; q += v * v;
    }
    float mu  = s * (1.0f / TT);
    float var = q * (1.0f / TT) - mu * mu;
    float sd  = sqrtf(var + 1e-5f);
    int i = b * CC + c;
    mean[i] = mu; stdv[i] = sd; rstd[i] = 1.0f / sd;
}

// ---------------- tok build: tiled transpose + normalize + tf32 ----------------
__global__ void build_tok_kernel(const float* __restrict__ xe,
                                 const float* __restrict__ xm,
                                 const float* __restrict__ mean,
                                 const float* __restrict__ rstd,
                                 const float* __restrict__ rw,
                                 const float* __restrict__ rb,
                                 uint32_t* __restrict__ tok) {
    __shared__ float tile[32][33];
    int b  = blockIdx.z;
    int t0 = blockIdx.x * 32;
    int c0 = blockIdx.y * 32;
    int tx = threadIdx.x, ty = threadIdx.y;
#pragma unroll
    for (int i = 0; i < 4; i++) {
        int t = t0 + ty + i * 8;
        int c = c0 + tx;
        float val = 0.f;
        if (t < TT && c < LTOK) {
            if (c < CC) {
                float xv = xe[((size_t)b * TT + t) * CC + c];
                int ii = b * CC + c;
                val = (xv - mean[ii]) * rstd[ii] * rw[c] + rb[c];
            } else {
                val = xm[((size_t)b * TT + t) * MM + (c - CC)];
            }
        }
        tile[ty + i * 8][tx] = val;
    }
    __syncthreads();
#pragma unroll
    for (int i = 0; i < 4; i++) {
        int l = c0 + ty + i * 8;
        int t = t0 + tx;
        if (l < LTOK && t < TT)
            tok[((size_t)b * LTOK + l) * TT + t] = f2tf32(tile[tx][ty + i * 8]);
    }
}

// ---------------- TF32 GEMM, cp.async 3-stage, 128x128x16, 64x32 warp tiles ----
#define ASTRIDE 20
#define BSTRIDE 136
#define ASTG (128 * ASTRIDE)     // 2560
#define BSTG (16 * BSTRIDE)      // 2176
#define STG  (ASTG + BSTG)       // 4736
#define NSTAGE 3
#define GEMM_SMEM (NSTAGE * STG * 4)

__device__ __forceinline__ void cpa16(uint32_t smaddr, const void* gptr, int sz) {
    asm volatile("cp.async.cg.shared.global [%0], [%1], 16, %2;\n"
                 :: "r"(smaddr), "l"(gptr), "r"(sz) : "memory");
}

__global__ __launch_bounds__(256, 2)
void gemm_tc(const uint32_t* __restrict__ A, const uint32_t* __restrict__ W,
             const float* __restrict__ bias,
             float* __restrict__ Cf, uint32_t* __restrict__ Ct,
             int N, int K, int Dout, int act) {
    extern __shared__ uint32_t sm[];
    const uint32_t smbase = (uint32_t)__cvta_generic_to_shared(sm);

    const int tid  = threadIdx.x;
    const int lane = tid & 31;
    const int wid  = tid >> 5;
    const int wRow = (wid & 1) * 64;
    const int wCol = (wid >> 1) * 32;
    const int gID  = lane >> 2;
    const int tg   = lane & 3;

    const int row0 = blockIdx.y * 128;
    const int col0 = blockIdx.x * 128;

    // A staging: thread -> row=tid>>1, kc = (tid&1)*8, two 16B chunks
    const int aRow = tid >> 1;
    const int aKc  = (tid & 1) * 8;
    const uint32_t* aSrc = A + (size_t)(row0 + aRow) * K + aKc;
    // B staging: thread -> krow=tid>>4, nc=(tid&15)*8, two 16B chunks
    const int bKr = tid >> 4;
    const int bNc = (tid & 15) * 8;
    const uint32_t* bSrc = W + (size_t)bKr * Dout + col0 + bNc;
    const int bOk0 = (col0 + bNc + 4  <= Dout) ? 16 : 0;
    const int bOk1 = (col0 + bNc + 8  <= Dout) ? 16 : 0;

    const uint32_t aDstBase = smbase + (aRow * ASTRIDE + aKc) * 4;
    const uint32_t bDstBase = smbase + (ASTG + bKr * BSTRIDE + bNc) * 4;

    float acc[4][4][4];
#pragma unroll
    for (int i = 0; i < 4; i++)
#pragma unroll
        for (int j = 0; j < 4; j++)
#pragma unroll
            for (int r = 0; r < 4; r++) acc[i][j][r] = 0.f;

    const int nIter = K >> 4;

#define ISSUE(stage, k0)                                                     \
    {                                                                        \
        uint32_t ad = aDstBase + (stage) * (STG * 4);                        \
        cpa16(ad,      aSrc + (k0),     16);                                 \
        cpa16(ad + 16, aSrc + (k0) + 4, 16);                                 \
        uint32_t bd = bDstBase + (stage) * (STG * 4);                        \
        cpa16(bd,      bSrc + (size_t)(k0) * Dout,     bOk0);                \
        cpa16(bd + 16, bSrc + (size_t)(k0) * Dout + 4, bOk1);                \
    }

    ISSUE(0, 0)
    asm volatile("cp.async.commit_group;\n" ::: "memory");
    ISSUE(1, 16)
    asm volatile("cp.async.commit_group;\n" ::: "memory");

    for (int t = 0; t < nIter; t++) {
        asm volatile("cp.async.wait_group 1;\n" ::: "memory");
        __syncthreads();
        const int buf = t % 3;
        const uint32_t* Ab = sm + buf * STG;
        const uint32_t* Bb = sm + buf * STG + ASTG;
#pragma unroll
        for (int ks = 0; ks < 2; ks++) {
            const int kb = ks * 8;
            uint32_t af[4][4];
            uint32_t bf[4][2];
#pragma unroll
            for (int i = 0; i < 4; i++) {
                int r = wRow + i * 16 + gID;
                af[i][0] = Ab[r * ASTRIDE + kb + tg];
                af[i][1] = Ab[(r + 8) * ASTRIDE + kb + tg];
                af[i][2] = Ab[r * ASTRIDE + kb + tg + 4];
                af[i][3] = Ab[(r + 8) * ASTRIDE + kb + tg + 4];
            }
#pragma unroll
            for (int j = 0; j < 4; j++) {
                int c = wCol + j * 8 + gID;
                bf[j][0] = Bb[(kb + tg) * BSTRIDE + c];
                bf[j][1] = Bb[(kb + tg + 4) * BSTRIDE + c];
            }
#pragma unroll
            for (int i = 0; i < 4; i++)
#pragma unroll
                for (int j = 0; j < 4; j++) {
                    asm volatile(
                        "mma.sync.aligned.m16n8k8.row.col.f32.tf32.tf32.f32 "
                        "{%0,%1,%2,%3}, {%4,%5,%6,%7}, {%8,%9}, {%0,%1,%2,%3};"
                        : "+f"(acc[i][j][0]), "+f"(acc[i][j][1]),
                          "+f"(acc[i][j][2]), "+f"(acc[i][j][3])
                        : "r"(af[i][0]), "r"(af[i][1]), "r"(af[i][2]), "r"(af[i][3]),
                          "r"(bf[j][0]), "r"(bf[j][1]));
                }
        }
        int nt = t + 2;
        if (nt < nIter) ISSUE(nt % 3, nt * 16)
        asm volatile("cp.async.commit_group;\n" ::: "memory");
    }
#undef ISSUE

    // epilogue
#pragma unroll
    for (int i = 0; i < 4; i++) {
#pragma unroll
        for (int half = 0; half < 2; half++) {
            int r = row0 + wRow + i * 16 + gID + half * 8;
            if (r >= N) continue;
#pragma unroll
            for (int j = 0; j < 4; j++) {
                int col = col0 + wCol + j * 8 + tg * 2;
                if (col >= Dout) continue;
                float v0 = acc[i][j][half * 2 + 0] + bias[col];
                float v1 = acc[i][j][half * 2 + 1] + bias[col + 1];
                if (act == 1) {
                    v0 = 1.0f / (1.0f + expf(-v0));
                    v1 = 1.0f / (1.0f + expf(-v1));
                } else if (act == 2) {
                    v0 = 0.5f * v0 * (1.0f + erff(v0 * 0.70710678118654752f));
                    v1 = 0.5f * v1 * (1.0f + erff(v1 * 0.70710678118654752f));
                }
                if (Cf)
                    *reinterpret_cast<float2*>(Cf + (size_t)r * Dout + col) =
                        make_float2(v0, v1);
                if (Ct) {
                    uint2 u; u.x = f2tf32(v0); u.y = f2tf32(v1);
                    *reinterpret_cast<uint2*>(Ct + (size_t)r * Dout + col) = u;
                }
            }
        }
    }
}

// ---------------- flow attention: 512 threads per (b,h), tf32 out ----------------
__global__ __launch_bounds__(512)
void attn_kernel(const float* __restrict__ q, const float* __restrict__ k,
                 const float* __restrict__ v, uint32_t* __restrict__ out) {
    int b = blockIdx.x >> 3, h = blockIdx.x & 7;
    const float* qp = q + ((size_t)b * LTOK) * DMOD + h * EH;
    const float* kp = k + ((size_t)b * LTOK) * DMOD + h * EH;
    const float* vp = v + ((size_t)b * LTOK) * DMOD + h * EH;
    uint32_t*    op = out + ((size_t)b * LTOK) * DMOD + h * EH;
    int tid = threadIdx.x, lane = tid & 31, wid = tid >> 5;   // 16 warps
    const float eps = 1e-6f;

    __shared__ float s_nr[LTOK], s_nc[LTOK], s_nrref[LTOK], s_ncref[LTOK];
    __shared__ float s_ksum[EH], s_qsum[EH], s_kns[EH], s_qns[EH];
    __shared__ float s_kv[EH][EH];
    __shared__ float s_pa[8][EH], s_pb[8][EH];
    __shared__ float s_red[16];

    // Phase A: column sums
    {
        int e = tid & 63, part = tid >> 6;   // 0..7
        float ka = 0.f, qa = 0.f;
        for (int s = part; s < LTOK; s += 8) {
            ka += kp[(size_t)s * DMOD + e];
            qa += qp[(size_t)s * DMOD + e];
        }
        s_pa[part][e] = ka;
        s_pb[part][e] = qa;
    }
    __syncthreads();
    if (tid < EH) {
        float a = 0.f, bsum = 0.f;
#pragma unroll
        for (int p = 0; p < 8; p++) { a += s_pa[p][tid]; bsum += s_pb[p][tid]; }
        s_ksum[tid] = a; s_qsum[tid] = bsum;
    }
    __syncthreads();

    // Phase B: nr, nc (warp per row)
    for (int r = wid; r < LTOK; r += 16) {
        float qv0 = qp[(size_t)r * DMOD + lane], qv1 = qp[(size_t)r * DMOD + lane + 32];
        float kv0 = kp[(size_t)r * DMOD + lane], kv1 = kp[(size_t)r * DMOD + lane + 32];
        float dq = (qv0 + eps) * (s_ksum[lane] + eps) + (qv1 + eps) * (s_ksum[lane + 32] + eps);
        float dk = (kv0 + eps) * (s_qsum[lane] + eps) + (kv1 + eps) * (s_qsum[lane + 32] + eps);
        for (int o = 16; o; o >>= 1) {
            dq += __shfl_xor_sync(0xffffffffu, dq, o);
            dk += __shfl_xor_sync(0xffffffffu, dk, o);
        }
        if (lane == 0) { s_nr[r] = 1.0f / dq; s_nc[r] = 1.0f / dk; }
    }
    __syncthreads();

    // Phase C: weighted column sums
    {
        int e = tid & 63, part = tid >> 6;
        float ka = 0.f, qa = 0.f;
        for (int s = part; s < LTOK; s += 8) {
            ka += kp[(size_t)s * DMOD + e] * s_nc[s];
            qa += qp[(size_t)s * DMOD + e] * s_nr[s];
        }
        s_pa[part][e] = ka;
        s_pb[part][e] = qa;
    }
    __syncthreads();
    if (tid < EH) {
        float a = 0.f, bsum = 0.f;
#pragma unroll
        for (int p = 0; p < 8; p++) { a += s_pa[p][tid]; bsum += s_pb[p][tid]; }
        s_kns[tid] = a; s_qns[tid] = bsum;
    }
    __syncthreads();

    // Phase D: nr_ref sigmoid, nc_ref logits
    for (int r = wid; r < LTOK; r += 16) {
        float qv0 = qp[(size_t)r * DMOD + lane], qv1 = qp[(size_t)r * DMOD + lane + 32];
        float kv0 = kp[(size_t)r * DMOD + lane], kv1 = kp[(size_t)r * DMOD + lane + 32];
        float dq = (qv0 + eps) * (s_kns[lane] + eps) + (qv1 + eps) * (s_kns[lane + 32] + eps);
        float dk = (kv0 + eps) * (s_qns[lane] + eps) + (kv1 + eps) * (s_qns[lane + 32] + eps);
        for (int o = 16; o; o >>= 1) {
            dq += __shfl_xor_sync(0xffffffffu, dq, o);
            dk += __shfl_xor_sync(0xffffffffu, dk, o);
        }
        if (lane == 0) {
            s_nrref[r] = 1.0f / (1.0f + expf(-dq));
            s_ncref[r] = dk;
        }
    }
    __syncthreads();

    // Phase E: softmax * Ls
    float lmax = -1e30f;
    for (int s = tid; s < LTOK; s += 512) lmax = fmaxf(lmax, s_ncref[s]);
    for (int o = 16; o; o >>= 1) lmax = fmaxf(lmax, __shfl_xor_sync(0xffffffffu, lmax, o));
    if (lane == 0) s_red[wid] = lmax;
    __syncthreads();
    if (tid == 0) {
        float m = s_red[0];
        for (int i = 1; i < 16; i++) m = fmaxf(m, s_red[i]);
        s_red[0] = m;
    }
    __syncthreads();
    lmax = s_red[0];
    __syncthreads();
    float lsum = 0.f;
    for (int s = tid; s < LTOK; s += 512) {
        float ev = expf(s_ncref[s] - lmax);
        s_ncref[s] = ev;
        lsum += ev;
    }
    for (int o = 16; o; o >>= 1) lsum += __shfl_xor_sync(0xffffffffu, lsum, o);
    if (lane == 0) s_red[wid] = lsum;
    __syncthreads();
    if (tid == 0) {
        float m = 0.f;
        for (int i = 0; i < 16; i++) m += s_red[i];
        s_red[0] = m;
    }
    __syncthreads();
    float scl = (float)LTOK / s_red[0];
    __syncthreads();
    for (int s = tid; s < LTOK; s += 512) s_ncref[s] *= scl;
    __syncthreads();

    // Phase F: kv[e][d]
    int e_own = tid >> 3;            // 0..63
    int d0    = (tid & 7) * 8;       // 0..56
    float acc[8];
#pragma unroll
    for (int i = 0; i < 8; i++) acc[i] = 0.f;
    for (int s0 = 0; s0 < LTOK; s0 += 8) {
        {
            int j = tid >> 6, e = tid & 63;
            int s = s0 + j;
            float kk = 0.f, vv = 0.f;
            if (s < LTOK) {
                kk = kp[(size_t)s * DMOD + e];
                vv = vp[(size_t)s * DMOD + e] * s_ncref[s];
            }
            s_pa[j][e] = kk;
            s_pb[j][e] = vv;
        }
        __syncthreads();
#pragma unroll
        for (int j = 0; j < 8; j++) {
            float ke = s_pa[j][e_own];
#pragma unroll
            for (int i = 0; i < 8; i++) acc[i] += ke * s_pb[j][d0 + i];
        }
        __syncthreads();
    }
#pragma unroll
    for (int i = 0; i < 8; i++) s_kv[e_own][d0 + i] = acc[i];
    __syncthreads();

    // Phase G: out rows via shfl broadcast
    for (int r = wid; r < LTOK; r += 16) {
        float qv0 = qp[(size_t)r * DMOD + lane];
        float qv1 = qp[(size_t)r * DMOD + lane + 32];
        float a0 = 0.f, a1 = 0.f;
#pragma unroll
        for (int e = 0; e < 32; e++) {
            float qe = __shfl_sync(0xffffffffu, qv0, e);
            a0 += qe * s_kv[e][lane];
            a1 += qe * s_kv[e][lane + 32];
        }
#pragma unroll
        for (int e = 0; e < 32; e++) {
            float qe = __shfl_sync(0xffffffffu, qv1, e);
            a0 += qe * s_kv[e + 32][lane];
            a1 += qe * s_kv[e + 32][lane + 32];
        }
        float sc = s_nr[r] * s_nrref[r];
        op[(size_t)r * DMOD + lane]      = f2tf32(a0 * sc);
        op[(size_t)r * DMOD + lane + 32] = f2tf32(a1 * sc);
    }
}

// ---------------- residual add + LayerNorm (+ tf32 copy) ----------------
__global__ __launch_bounds__(256)
void add_ln_kernel(float* __restrict__ x, const float* __restrict__ res,
                   const float* __restrict__ w, const float* __restrict__ bb,
                   uint32_t* __restrict__ xt, int useRes) {
    __shared__ float s_s[8], s_q[8];
    int row = blockIdx.x, tid = threadIdx.x, lane = tid & 31, wid = tid >> 5;
    size_t base = (size_t)row * DMOD;
    float v0 = x[base + tid], v1 = x[base + tid + 256];
    if (useRes) { v0 += res[base + tid]; v1 += res[base + tid + 256]; }
    float s = v0 + v1, q = v0 * v0 + v1 * v1;
    for (int o = 16; o; o >>= 1) {
        s += __shfl_xor_sync(0xffffffffu, s, o);
        q += __shfl_xor_sync(0xffffffffu, q, o);
    }
    if (lane == 0) { s_s[wid] = s; s_q[wid] = q; }
    __syncthreads();
    if (tid == 0) {
        float ss = 0.f, qq = 0.f;
        for (int i = 0; i < 8; i++) { ss += s_s[i]; qq += s_q[i]; }
        s_s[0] = ss; s_q[0] = qq;
    }
    __syncthreads();
    float mu  = s_s[0] * (1.0f / DMOD);
    float var = s_q[0] * (1.0f / DMOD) - mu * mu;
    float r   = rsqrtf(var + 1e-5f);
    float o0 = (v0 - mu) * r * w[tid] + bb[tid];
    float o1 = (v1 - mu) * r * w[tid + 256] + bb[tid + 256];
    x[base + tid]        = o0;
    x[base + tid + 256]  = o1;
    xt[base + tid]       = f2tf32(o0);
    xt[base + tid + 256] = f2tf32(o1);
}

// ---------------- output: tiled transpose + RevIN denorm ----------------
__global__ void out_kernel(const float* __restrict__ proj,
                           const float* __restrict__ rw, const float* __restrict__ rb,
                           const float* __restrict__ mean, const float* __restrict__ stdv,
                           float* __restrict__ out) {
    __shared__ float tile[32][33];
    int b  = blockIdx.z;
    int c0 = blockIdx.x * 32;
    int t0 = blockIdx.y * 32;
    int tx = threadIdx.x, ty = threadIdx.y;
#pragma unroll
    for (int i = 0; i < 4; i++) {
        int c = c0 + ty + i * 8;
        int t = t0 + tx;
        float val = 0.f;
        if (c < CC && t < PRED)
            val = proj[((size_t)b * LTOK + c) * PRED + t];
        tile[ty + i * 8][tx] = val;
    }
    __syncthreads();
#pragma unroll
    for (int i = 0; i < 4; i++) {
        int t = t0 + ty + i * 8;
        int c = c0 + tx;
        if (t < PRED && c < CC) {
            float p  = tile[tx][ty + i * 8];
            float vv = (p - rb[c]) / (rw[c] + 1e-10f);
            out[((size_t)b * PRED + t) * CC + c] = vv * stdv[b * CC + c] + mean[b * CC + c];
        }
    }
}

// ---------------- host orchestration ----------------
static inline void launch_gemm(const uint32_t* A, const uint32_t* W, const float* bias,
                               float* Cf, uint32_t* Ct, int N, int K, int Dout, int act) {
    dim3 grid((Dout + 127) / 128, (N + 127) / 128);
    gemm_tc<<<grid, 256, GEMM_SMEM>>>(A, W, bias, Cf, Ct, N, K, Dout, act);
}

extern "C" void kernel_launch(void* const* d_in, const int* in_sizes, int n_in,
                              void* d_out, int out_size) {
    const float* x_enc   = (const float*)d_in[0];
    const float* x_mark  = (const float*)d_in[1];
    const float* revin_w = (const float*)d_in[4];
    const float* revin_b = (const float*)d_in[5];
    const float* emb_W   = (const float*)d_in[6];
    const float* emb_b   = (const float*)d_in[7];
    const float* Wq = (const float*)d_in[8],  *bq = (const float*)d_in[9];
    const float* Wk = (const float*)d_in[10], *bk = (const float*)d_in[11];
    const float* Wv = (const float*)d_in[12], *bv = (const float*)d_in[13];
    const float* Wo = (const float*)d_in[14], *bo = (const float*)d_in[15];
    const float* ff1_W = (const float*)d_in[16], *ff1_b = (const float*)d_in[17];
    const float* ff2_W = (const float*)d_in[18], *ff2_b = (const float*)d_in[19];
    const float* ln1_w = (const float*)d_in[20], *ln1_b = (const float*)d_in[21];
    const float* ln2_w = (const float*)d_in[22], *ln2_b = (const float*)d_in[23];
    const float* lnf_w = (const float*)d_in[24], *lnf_b = (const float*)d_in[25];
    const float* proj_W = (const float*)d_in[26], *proj_b = (const float*)d_in[27];

    static int smem_set = 0;
    if (!smem_set) {
        cudaFuncSetAttribute(gemm_tc, cudaFuncAttributeMaxDynamicSharedMemorySize, GEMM_SMEM);
        smem_set = 1;
    }

    uint32_t *tok, *xt, *a, *ff;
    float *x, *q, *k, *v, *tmp, *proj, *mean, *stdv, *rstd;
    uint32_t *wemb_t, *wq_t, *wk_t, *wv_t, *wo_t, *wff1_t, *wff2_t, *wproj_t;
    cudaGetSymbolAddress((void**)&tok,  g_tok);
    cudaGetSymbolAddress((void**)&x,    g_x);
    cudaGetSymbolAddress((void**)&xt,   g_xt);
    cudaGetSymbolAddress((void**)&q,    g_q);
    cudaGetSymbolAddress((void**)&k,    g_k);
    cudaGetSymbolAddress((void**)&v,    g_v);
    cudaGetSymbolAddress((void**)&a,    g_a);
    cudaGetSymbolAddress((void**)&tmp,  g_tmp);
    cudaGetSymbolAddress((void**)&ff,   g_ff);
    cudaGetSymbolAddress((void**)&proj, g_proj);
    cudaGetSymbolAddress((void**)&mean, g_mean);
    cudaGetSymbolAddress((void**)&stdv, g_std);
    cudaGetSymbolAddress((void**)&rstd, g_rstd);
    cudaGetSymbolAddress((void**)&wemb_t,  g_wemb_t);
    cudaGetSymbolAddress((void**)&wq_t,    g_wq_t);
    cudaGetSymbolAddress((void**)&wk_t,    g_wk_t);
    cudaGetSymbolAddress((void**)&wv_t,    g_wv_t);
    cudaGetSymbolAddress((void**)&wo_t,    g_wo_t);
    cudaGetSymbolAddress((void**)&wff1_t,  g_wff1_t);
    cudaGetSymbolAddress((void**)&wff2_t,  g_wff2_t);
    cudaGetSymbolAddress((void**)&wproj_t, g_wproj_t);

    // weight conversion (tf32)
    cvt_kernel<<<512, 256>>>(emb_W,  wemb_t,  TT * DMOD);
    cvt_kernel<<<512, 256>>>(Wq,     wq_t,    LAYERS * DMOD * DMOD);
    cvt_kernel<<<512, 256>>>(Wk,     wk_t,    LAYERS * DMOD * DMOD);
    cvt_kernel<<<512, 256>>>(Wv,     wv_t,    LAYERS * DMOD * DMOD);
    cvt_kernel<<<512, 256>>>(Wo,     wo_t,    LAYERS * DMOD * DMOD);
    cvt_kernel<<<512, 256>>>(ff1_W,  wff1_t,  LAYERS * DMOD * FFD);
    cvt_kernel<<<512, 256>>>(ff2_W,  wff2_t,  LAYERS * FFD * DMOD);
    cvt_kernel<<<512, 256>>>(proj_W, wproj_t, DMOD * PRED);

    revin_stats_kernel<<<dim3((CC + 127) / 128, BB), 128>>>(x_enc, mean, stdv, rstd);
    {
        dim3 grid((TT + 31) / 32, (LTOK + 31) / 32, BB);
        build_tok_kernel<<<grid, dim3(32, 8)>>>(x_enc, x_mark, mean, rstd,
                                                revin_w, revin_b, tok);
    }
    // embedding: out both fp32 (residual chain) and tf32 (QKV A input)
    launch_gemm(tok, wemb_t, emb_b, x, xt, NROW, TT, DMOD, 0);

    for (int l = 0; l < LAYERS; l++) {
        const uint32_t* wql = wq_t + (size_t)l * DMOD * DMOD;
        const uint32_t* wkl = wk_t + (size_t)l * DMOD * DMOD;
        const uint32_t* wvl = wv_t + (size_t)l * DMOD * DMOD;
        const uint32_t* wol = wo_t + (size_t)l * DMOD * DMOD;
        launch_gemm(xt, wql, bq + l * DMOD, q, nullptr, NROW, DMOD, DMOD, 1);
        launch_gemm(xt, wkl, bk + l * DMOD, k, nullptr, NROW, DMOD, DMOD, 1);
        launch_gemm(xt, wvl, bv + l * DMOD, v, nullptr, NROW, DMOD, DMOD, 0);
        attn_kernel<<<BB * HH, 512>>>(q, k, v, a);
        launch_gemm(a, wol, bo + l * DMOD, tmp, nullptr, NROW, DMOD, DMOD, 0);
        add_ln_kernel<<<NROW, 256>>>(x, tmp, ln1_w + l * DMOD, ln1_b + l * DMOD, xt, 1);
        launch_gemm(xt, wff1_t + (size_t)l * DMOD * FFD, ff1_b + l * FFD,
                    nullptr, ff, NROW, DMOD, FFD, 2);
        launch_gemm(ff, wff2_t + (size_t)l * FFD * DMOD, ff2_b + l * DMOD,
                    tmp, nullptr, NROW, FFD, DMOD, 0);
        add_ln_kernel<<<NROW, 256>>>(x, tmp, ln2_w + l * DMOD, ln2_b + l * DMOD, xt, 1);
    }
    add_ln_kernel<<<NROW, 256>>>(x, nullptr, lnf_w, lnf_b, xt, 0);
    launch_gemm(xt, wproj_t, proj_b, proj, nullptr, NROW, DMOD, PRED, 0);
    {
        dim3 grid((CC + 31) / 32, (PRED + 31) / 32, BB);
        out_kernel<<<grid, dim3(32, 8)>>>(proj, revin_w, revin_b, mean, stdv,
                                          (float*)d_out);
    }
}

// round 5
// speedup vs baseline: 1.5974x; 1.3406x over previous
#include <cuda_runtime.h>
#include <cuda_fp16.h>
#include <math.h>
#include <stdint.h>

// ---------------- problem constants ----------------
#define BB    32
#define TT    720
#define CC    862
#define MM    4
#define LTOK  866
#define DMOD  512
#define HH    8
#define EH    64
#define FFD   2048
#define PRED  720
#define NROW  (BB * LTOK)        // 27712
#define NPAD  27776              // 217 * 128
#define LAYERS 3
#define TKP   736                // TT padded to 32
#define PRJP  768                // PRED padded to 128

// ---------------- device scratch ----------------
__device__ __half g_tok [NPAD * TKP];        // half tokens [row][TKP]
__device__ float  g_x   [NROW * DMOD];
__device__ __half g_xt  [NPAD * DMOD];       // half copy of x
__device__ float  g_q   [NROW * DMOD];
__device__ float  g_k   [NROW * DMOD];
__device__ float  g_v   [NROW * DMOD];
__device__ __half g_a   [NPAD * DMOD];       // attn out (half)
__device__ float  g_tmp [NROW * DMOD];
__device__ __half g_ff  [NPAD * FFD];        // gelu out (half)
__device__ float  g_proj[NROW * PRED];
__device__ float  g_mean[BB * CC];
__device__ float  g_std [BB * CC];
__device__ float  g_rstd[BB * CC];
// half transposed weights: [Dout][K]
__device__ __half g_wemb [DMOD * TKP];
__device__ __half g_wq_t [LAYERS * DMOD * DMOD];
__device__ __half g_wk_t [LAYERS * DMOD * DMOD];
__device__ __half g_wv_t [LAYERS * DMOD * DMOD];
__device__ __half g_wo_t [LAYERS * DMOD * DMOD];
__device__ __half g_wff1 [LAYERS * FFD * DMOD];
__device__ __half g_wff2 [LAYERS * DMOD * FFD];
__device__ __half g_wproj[PRJP * DMOD];

// ---------------- weight convert: fp32 [K][Dout] -> half [DP][KP] (transpose+pad) ----
__global__ void cvt_w_kernel(const float* __restrict__ src, __half* __restrict__ dst,
                             int K, int Dout, int KP, int DP) {
    __shared__ float tile[32][33];
    int k0 = blockIdx.x * 32, d0 = blockIdx.y * 32;
    int tx = threadIdx.x, ty = threadIdx.y;
#pragma unroll
    for (int i = 0; i < 4; i++) {
        int k = k0 + ty + i * 8, d = d0 + tx;
        float v = (k < K && d < Dout) ? src[(size_t)k * Dout + d] : 0.f;
        tile[ty + i * 8][tx] = v;
    }
    __syncthreads();
#pragma unroll
    for (int i = 0; i < 4; i++) {
        int d = d0 + ty + i * 8, k = k0 + tx;
        if (d < DP && k < KP)
            dst[(size_t)d * KP + k] = __float2half(tile[tx][ty + i * 8]);
    }
}

// ---------------- RevIN stats ----------------
__global__ void revin_stats_kernel(const float* __restrict__ xe,
                                   float* __restrict__ mean,
                                   float* __restrict__ stdv,
                                   float* __restrict__ rstd) {
    int c = blockIdx.x * 128 + threadIdx.x;
    int b = blockIdx.y;
    if (c >= CC) return;
    const float* p = xe + (size_t)b * TT * CC + c;
    float s = 0.f, q = 0.f;
    for (int t = 0; t < TT; t++) {
        float v = p[(size_t)t * CC];
        s += v; q += v * v;
    }
    float mu  = s * (1.0f / TT);
    float var = q * (1.0f / TT) - mu * mu;
    float sd  = sqrtf(var + 1e-5f);
    int i = b * CC + c;
    mean[i] = mu; stdv[i] = sd; rstd[i] = 1.0f / sd;
}

// ---------------- tok build: tiled transpose + normalize -> half ----------------
__global__ void build_tok_kernel(const float* __restrict__ xe,
                                 const float* __restrict__ xm,
                                 const float* __restrict__ mean,
                                 const float* __restrict__ rstd,
                                 const float* __restrict__ rw,
                                 const float* __restrict__ rb,
                                 __half* __restrict__ tok) {
    __shared__ float tile[32][33];
    int b  = blockIdx.z;
    int t0 = blockIdx.x * 32;
    int c0 = blockIdx.y * 32;
    int tx = threadIdx.x, ty = threadIdx.y;
#pragma unroll
    for (int i = 0; i < 4; i++) {
        int t = t0 + ty + i * 8;
        int c = c0 + tx;
        float val = 0.f;
        if (t < TT && c < LTOK) {
            if (c < CC) {
                float xv = xe[((size_t)b * TT + t) * CC + c];
                int ii = b * CC + c;
                val = (xv - mean[ii]) * rstd[ii] * rw[c] + rb[c];
            } else {
                val = xm[((size_t)b * TT + t) * MM + (c - CC)];
            }
        }
        tile[ty + i * 8][tx] = val;
    }
    __syncthreads();
#pragma unroll
    for (int i = 0; i < 4; i++) {
        int l = c0 + ty + i * 8;
        int t = t0 + tx;
        if (l < LTOK && t < TT)
            tok[((size_t)b * LTOK + l) * TKP + t] = __float2half(tile[tx][ty + i * 8]);
    }
}

// ---------------- FP16 GEMM, cp.async 3-stage, 128x128x32, 64x32 warp tiles ----
#define KTILE 32
#define ASTR  20                  // u32 words per 32-half row (16 + 4 pad)
#define HSTG  2560                // words per A (or B) stage: 128*20
#define STGW  (2 * HSTG)          // 5120 words per stage
#define GEMM_SMEM (3 * STGW * 4)  // 61440 B

__device__ __forceinline__ void cpa16(uint32_t smaddr, const void* gptr) {
    asm volatile("cp.async.cg.shared.global [%0], [%1], 16;\n"
                 :: "r"(smaddr), "l"(gptr) : "memory");
}

__global__ __launch_bounds__(256, 2)
void gemm_f16(const __half* __restrict__ A, const __half* __restrict__ W,
              const float* __restrict__ bias,
              float* __restrict__ Cf, __half* __restrict__ Ct,
              int N, int K, int Dout, int act) {
    extern __shared__ uint32_t sm[];
    const uint32_t smbase = (uint32_t)__cvta_generic_to_shared(sm);

    const int tid  = threadIdx.x;
    const int lane = tid & 31;
    const int wid  = tid >> 5;
    const int wRow = (wid & 1) * 64;
    const int wCol = (wid >> 1) * 32;
    const int gID  = lane >> 2;
    const int tg   = lane & 3;

    const int row0 = blockIdx.y * 128;
    const int col0 = blockIdx.x * 128;

    // staging: thread -> row = tid>>1, half-offset = (tid&1)*16, two 16B chunks
    const int sRow = tid >> 1;
    const int sW   = (tid & 1) * 8;          // word offset in row
    const __half* aSrc = A + (size_t)(row0 + sRow) * K + (tid & 1) * 16;
    const __half* bSrc = W + (size_t)(col0 + sRow) * K + (tid & 1) * 16;
    const uint32_t aDst = smbase + (sRow * ASTR + sW) * 4;
    const uint32_t bDst = smbase + (HSTG + sRow * ASTR + sW) * 4;

    float acc[4][4][4];
#pragma unroll
    for (int i = 0; i < 4; i++)
#pragma unroll
        for (int j = 0; j < 4; j++)
#pragma unroll
            for (int r = 0; r < 4; r++) acc[i][j][r] = 0.f;

    const int nIter = K >> 5;

#define ISSUE(stage, t)                                          \
    {                                                            \
        uint32_t ad = aDst + (stage) * (STGW * 4);               \
        const __half* ag = aSrc + (size_t)(t) * KTILE;           \
        cpa16(ad, ag); cpa16(ad + 16, ag + 8);                   \
        uint32_t bd = bDst + (stage) * (STGW * 4);               \
        const __half* bg = bSrc + (size_t)(t) * KTILE;           \
        cpa16(bd, bg); cpa16(bd + 16, bg + 8);                   \
    }

    ISSUE(0, 0)
    asm volatile("cp.async.commit_group;\n" ::: "memory");
    ISSUE(1, 1)
    asm volatile("cp.async.commit_group;\n" ::: "memory");

    for (int t = 0; t < nIter; t++) {
        asm volatile("cp.async.wait_group 1;\n" ::: "memory");
        __syncthreads();
        const int buf = t % 3;
        const uint32_t* Ab = sm + buf * STGW;
        const uint32_t* Bb = Ab + HSTG;
#pragma unroll
        for (int kc = 0; kc < 2; kc++) {
            const int kw = kc * 8;
            uint32_t af[4][4];
            uint32_t bf[4][2];
#pragma unroll
            for (int i = 0; i < 4; i++) {
                int r = wRow + i * 16 + gID;
                af[i][0] = Ab[r * ASTR + kw + tg];
                af[i][1] = Ab[(r + 8) * ASTR + kw + tg];
                af[i][2] = Ab[r * ASTR + kw + tg + 4];
                af[i][3] = Ab[(r + 8) * ASTR + kw + tg + 4];
            }
#pragma unroll
            for (int j = 0; j < 4; j++) {
                int c = wCol + j * 8 + gID;
                bf[j][0] = Bb[c * ASTR + kw + tg];
                bf[j][1] = Bb[c * ASTR + kw + tg + 4];
            }
#pragma unroll
            for (int i = 0; i < 4; i++)
#pragma unroll
                for (int j = 0; j < 4; j++) {
                    asm volatile(
                        "mma.sync.aligned.m16n8k16.row.col.f32.f16.f16.f32 "
                        "{%0,%1,%2,%3}, {%4,%5,%6,%7}, {%8,%9}, {%0,%1,%2,%3};"
                        : "+f"(acc[i][j][0]), "+f"(acc[i][j][1]),
                          "+f"(acc[i][j][2]), "+f"(acc[i][j][3])
                        : "r"(af[i][0]), "r"(af[i][1]), "r"(af[i][2]), "r"(af[i][3]),
                          "r"(bf[j][0]), "r"(bf[j][1]));
                }
        }
        int nt = t + 2;
        if (nt < nIter) ISSUE(nt % 3, nt)
        asm volatile("cp.async.commit_group;\n" ::: "memory");
    }
#undef ISSUE

    // epilogue
#pragma unroll
    for (int i = 0; i < 4; i++) {
#pragma unroll
        for (int half = 0; half < 2; half++) {
            int r = row0 + wRow + i * 16 + gID + half * 8;
            if (r >= N) continue;
#pragma unroll
            for (int j = 0; j < 4; j++) {
                int col = col0 + wCol + j * 8 + tg * 2;
                if (col >= Dout) continue;
                float v0 = acc[i][j][half * 2 + 0] + bias[col];
                float v1 = acc[i][j][half * 2 + 1] + bias[col + 1];
                if (act == 1) {
                    v0 = 1.0f / (1.0f + expf(-v0));
                    v1 = 1.0f / (1.0f + expf(-v1));
                } else if (act == 2) {
                    v0 = 0.5f * v0 * (1.0f + erff(v0 * 0.70710678118654752f));
                    v1 = 0.5f * v1 * (1.0f + erff(v1 * 0.70710678118654752f));
                }
                if (Cf)
                    *reinterpret_cast<float2*>(Cf + (size_t)r * Dout + col) =
                        make_float2(v0, v1);
                if (Ct)
                    *reinterpret_cast<__half2*>(Ct + (size_t)r * Dout + col) =
                        __floats2half2_rn(v0, v1);
            }
        }
    }
}

// ---------------- flow attention: 512 threads per (b,h), half out ----------------
__global__ __launch_bounds__(512)
void attn_kernel(const float* __restrict__ q, const float* __restrict__ k,
                 const float* __restrict__ v, __half* __restrict__ out) {
    int b = blockIdx.x >> 3, h = blockIdx.x & 7;
    const float* qp = q + ((size_t)b * LTOK) * DMOD + h * EH;
    const float* kp = k + ((size_t)b * LTOK) * DMOD + h * EH;
    const float* vp = v + ((size_t)b * LTOK) * DMOD + h * EH;
    __half*      op = out + ((size_t)b * LTOK) * DMOD + h * EH;
    int tid = threadIdx.x, lane = tid & 31, wid = tid >> 5;
    const float eps = 1e-6f;

    __shared__ float s_nr[LTOK], s_nc[LTOK], s_nrref[LTOK], s_ncref[LTOK];
    __shared__ float s_ksum[EH], s_qsum[EH], s_kns[EH], s_qns[EH];
    __shared__ float s_kv[EH][EH];
    __shared__ float s_pa[8][EH], s_pb[8][EH];
    __shared__ float s_red[16];

    {
        int e = tid & 63, part = tid >> 6;
        float ka = 0.f, qa = 0.f;
        for (int s = part; s < LTOK; s += 8) {
            ka += kp[(size_t)s * DMOD + e];
            qa += qp[(size_t)s * DMOD + e];
        }
        s_pa[part][e] = ka;
        s_pb[part][e] = qa;
    }
    __syncthreads();
    if (tid < EH) {
        float a = 0.f, bs = 0.f;
#pragma unroll
        for (int p = 0; p < 8; p++) { a += s_pa[p][tid]; bs += s_pb[p][tid]; }
        s_ksum[tid] = a; s_qsum[tid] = bs;
    }
    __syncthreads();

    for (int r = wid; r < LTOK; r += 16) {
        float qv0 = qp[(size_t)r * DMOD + lane], qv1 = qp[(size_t)r * DMOD + lane + 32];
        float kv0 = kp[(size_t)r * DMOD + lane], kv1 = kp[(size_t)r * DMOD + lane + 32];
        float dq = (qv0 + eps) * (s_ksum[lane] + eps) + (qv1 + eps) * (s_ksum[lane + 32] + eps);
        float dk = (kv0 + eps) * (s_qsum[lane] + eps) + (kv1 + eps) * (s_qsum[lane + 32] + eps);
        for (int o = 16; o; o >>= 1) {
            dq += __shfl_xor_sync(0xffffffffu, dq, o);
            dk += __shfl_xor_sync(0xffffffffu, dk, o);
        }
        if (lane == 0) { s_nr[r] = 1.0f / dq; s_nc[r] = 1.0f / dk; }
    }
    __syncthreads();

    {
        int e = tid & 63, part = tid >> 6;
        float ka = 0.f, qa = 0.f;
        for (int s = part; s < LTOK; s += 8) {
            ka += kp[(size_t)s * DMOD + e] * s_nc[s];
            qa += qp[(size_t)s * DMOD + e] * s_nr[s];
        }
        s_pa[part][e] = ka;
        s_pb[part][e] = qa;
    }
    __syncthreads();
    if (tid < EH) {
        float a = 0.f, bs = 0.f;
#pragma unroll
        for (int p = 0; p < 8; p++) { a += s_pa[p][tid]; bs += s_pb[p][tid]; }
        s_kns[tid] = a; s_qns[tid] = bs;
    }
    __syncthreads();

    for (int r = wid; r < LTOK; r += 16) {
        float qv0 = qp[(size_t)r * DMOD + lane], qv1 = qp[(size_t)r * DMOD + lane + 32];
        float kv0 = kp[(size_t)r * DMOD + lane], kv1 = kp[(size_t)r * DMOD + lane + 32];
        float dq = (qv0 + eps) * (s_kns[lane] + eps) + (qv1 + eps) * (s_kns[lane + 32] + eps);
        float dk = (kv0 + eps) * (s_qns[lane] + eps) + (kv1 + eps) * (s_qns[lane + 32] + eps);
        for (int o = 16; o; o >>= 1) {
            dq += __shfl_xor_sync(0xffffffffu, dq, o);
            dk += __shfl_xor_sync(0xffffffffu, dk, o);
        }
        if (lane == 0) {
            s_nrref[r] = 1.0f / (1.0f + expf(-dq));
            s_ncref[r] = dk;
        }
    }
    __syncthreads();

    float lmax = -1e30f;
    for (int s = tid; s < LTOK; s += 512) lmax = fmaxf(lmax, s_ncref[s]);
    for (int o = 16; o; o >>= 1) lmax = fmaxf(lmax, __shfl_xor_sync(0xffffffffu, lmax, o));
    if (lane == 0) s_red[wid] = lmax;
    __syncthreads();
    if (tid == 0) {
        float m = s_red[0];
        for (int i = 1; i < 16; i++) m = fmaxf(m, s_red[i]);
        s_red[0] = m;
    }
    __syncthreads();
    lmax = s_red[0];
    __syncthreads();
    float lsum = 0.f;
    for (int s = tid; s < LTOK; s += 512) {
        float ev = expf(s_ncref[s] - lmax);
        s_ncref[s] = ev;
        lsum += ev;
    }
    for (int o = 16; o; o >>= 1) lsum += __shfl_xor_sync(0xffffffffu, lsum, o);
    if (lane == 0) s_red[wid] = lsum;
    __syncthreads();
    if (tid == 0) {
        float m = 0.f;
        for (int i = 0; i < 16; i++) m += s_red[i];
        s_red[0] = m;
    }
    __syncthreads();
    float scl = (float)LTOK / s_red[0];
    __syncthreads();
    for (int s = tid; s < LTOK; s += 512) s_ncref[s] *= scl;
    __syncthreads();

    int e_own = tid >> 3;
    int d0    = (tid & 7) * 8;
    float acc[8];
#pragma unroll
    for (int i = 0; i < 8; i++) acc[i] = 0.f;
    for (int s0 = 0; s0 < LTOK; s0 += 8) {
        {
            int j = tid >> 6, e = tid & 63;
            int s = s0 + j;
            float kk = 0.f, vv = 0.f;
            if (s < LTOK) {
                kk = kp[(size_t)s * DMOD + e];
                vv = vp[(size_t)s * DMOD + e] * s_ncref[s];
            }
            s_pa[j][e] = kk;
            s_pb[j][e] = vv;
        }
        __syncthreads();
#pragma unroll
        for (int j = 0; j < 8; j++) {
            float ke = s_pa[j][e_own];
#pragma unroll
            for (int i = 0; i < 8; i++) acc[i] += ke * s_pb[j][d0 + i];
        }
        __syncthreads();
    }
#pragma unroll
    for (int i = 0; i < 8; i++) s_kv[e_own][d0 + i] = acc[i];
    __syncthreads();

    for (int r = wid; r < LTOK; r += 16) {
        float qv0 = qp[(size_t)r * DMOD + lane];
        float qv1 = qp[(size_t)r * DMOD + lane + 32];
        float a0 = 0.f, a1 = 0.f;
#pragma unroll
        for (int e = 0; e < 32; e++) {
            float qe = __shfl_sync(0xffffffffu, qv0, e);
            a0 += qe * s_kv[e][lane];
            a1 += qe * s_kv[e][lane + 32];
        }
#pragma unroll
        for (int e = 0; e < 32; e++) {
            float qe = __shfl_sync(0xffffffffu, qv1, e);
            a0 += qe * s_kv[e + 32][lane];
            a1 += qe * s_kv[e + 32][lane + 32];
        }
        float sc = s_nr[r] * s_nrref[r];
        op[(size_t)r * DMOD + lane]      = __float2half(a0 * sc);
        op[(size_t)r * DMOD + lane + 32] = __float2half(a1 * sc);
    }
}

// ---------------- residual add + LayerNorm (+ half copy) ----------------
__global__ __launch_bounds__(256)
void add_ln_kernel(float* __restrict__ x, const float* __restrict__ res,
                   const float* __restrict__ w, const float* __restrict__ bb,
                   __half* __restrict__ xt, int useRes) {
    __shared__ float s_s[8], s_q[8];
    int row = blockIdx.x, tid = threadIdx.x, lane = tid & 31, wid = tid >> 5;
    size_t base = (size_t)row * DMOD;
    float v0 = x[base + tid], v1 = x[base + tid + 256];
    if (useRes) { v0 += res[base + tid]; v1 += res[base + tid + 256]; }
    float s = v0 + v1, q = v0 * v0 + v1 * v1;
    for (int o = 16; o; o >>= 1) {
        s += __shfl_xor_sync(0xffffffffu, s, o);
        q += __shfl_xor_sync(0xffffffffu, q, o);
    }
    if (lane == 0) { s_s[wid] = s; s_q[wid] = q; }
    __syncthreads();
    if (tid == 0) {
        float ss = 0.f, qq = 0.f;
        for (int i = 0; i < 8; i++) { ss += s_s[i]; qq += s_q[i]; }
        s_s[0] = ss; s_q[0] = qq;
    }
    __syncthreads();
    float mu  = s_s[0] * (1.0f / DMOD);
    float var = s_q[0] * (1.0f / DMOD) - mu * mu;
    float r   = rsqrtf(var + 1e-5f);
    float o0 = (v0 - mu) * r * w[tid] + bb[tid];
    float o1 = (v1 - mu) * r * w[tid + 256] + bb[tid + 256];
    x[base + tid]        = o0;
    x[base + tid + 256]  = o1;
    xt[base + tid]       = __float2half(o0);
    xt[base + tid + 256] = __float2half(o1);
}

// ---------------- output: tiled transpose + RevIN denorm ----------------
__global__ void out_kernel(const float* __restrict__ proj,
                           const float* __restrict__ rw, const float* __restrict__ rb,
                           const float* __restrict__ mean, const float* __restrict__ stdv,
                           float* __restrict__ out) {
    __shared__ float tile[32][33];
    int b  = blockIdx.z;
    int c0 = blockIdx.x * 32;
    int t0 = blockIdx.y * 32;
    int tx = threadIdx.x, ty = threadIdx.y;
#pragma unroll
    for (int i = 0; i < 4; i++) {
        int c = c0 + ty + i * 8;
        int t = t0 + tx;
        float val = 0.f;
        if (c < CC && t < PRED)
            val = proj[((size_t)b * LTOK + c) * PRED + t];
        tile[ty + i * 8][tx] = val;
    }
    __syncthreads();
#pragma unroll
    for (int i = 0; i < 4; i++) {
        int t = t0 + ty + i * 8;
        int c = c0 + tx;
        if (t < PRED && c < CC) {
            float p  = tile[tx][ty + i * 8];
            float vv = (p - rb[c]) / (rw[c] + 1e-10f);
            out[((size_t)b * PRED + t) * CC + c] = vv * stdv[b * CC + c] + mean[b * CC + c];
        }
    }
}

// ---------------- host orchestration ----------------
static inline void launch_gemm(const __half* A, const __half* W, const float* bias,
                               float* Cf, __half* Ct, int N, int K, int Dout, int act) {
    dim3 grid((Dout + 127) / 128, (N + 127) / 128);
    gemm_f16<<<grid, 256, GEMM_SMEM>>>(A, W, bias, Cf, Ct, N, K, Dout, act);
}

extern "C" void kernel_launch(void* const* d_in, const int* in_sizes, int n_in,
                              void* d_out, int out_size) {
    const float* x_enc   = (const float*)d_in[0];
    const float* x_mark  = (const float*)d_in[1];
    const float* revin_w = (const float*)d_in[4];
    const float* revin_b = (const float*)d_in[5];
    const float* emb_W   = (const float*)d_in[6];
    const float* emb_b   = (const float*)d_in[7];
    const float* Wq = (const float*)d_in[8],  *bq = (const float*)d_in[9];
    const float* Wk = (const float*)d_in[10], *bk = (const float*)d_in[11];
    const float* Wv = (const float*)d_in[12], *bv = (const float*)d_in[13];
    const float* Wo = (const float*)d_in[14], *bo = (const float*)d_in[15];
    const float* ff1_W = (const float*)d_in[16], *ff1_b = (const float*)d_in[17];
    const float* ff2_W = (const float*)d_in[18], *ff2_b = (const float*)d_in[19];
    const float* ln1_w = (const float*)d_in[20], *ln1_b = (const float*)d_in[21];
    const float* ln2_w = (const float*)d_in[22], *ln2_b = (const float*)d_in[23];
    const float* lnf_w = (const float*)d_in[24], *lnf_b = (const float*)d_in[25];
    const float* proj_W = (const float*)d_in[26], *proj_b = (const float*)d_in[27];

    static int smem_set = 0;
    if (!smem_set) {
        cudaFuncSetAttribute(gemm_f16, cudaFuncAttributeMaxDynamicSharedMemorySize, GEMM_SMEM);
        smem_set = 1;
    }

    __half *tok, *xt, *a, *ff;
    float *x, *q, *k, *v, *tmp, *proj, *mean, *stdv, *rstd;
    __half *wemb, *wq_t, *wk_t, *wv_t, *wo_t, *wff1, *wff2, *wproj;
    cudaGetSymbolAddress((void**)&tok,  g_tok);
    cudaGetSymbolAddress((void**)&x,    g_x);
    cudaGetSymbolAddress((void**)&xt,   g_xt);
    cudaGetSymbolAddress((void**)&q,    g_q);
    cudaGetSymbolAddress((void**)&k,    g_k);
    cudaGetSymbolAddress((void**)&v,    g_v);
    cudaGetSymbolAddress((void**)&a,    g_a);
    cudaGetSymbolAddress((void**)&tmp,  g_tmp);
    cudaGetSymbolAddress((void**)&ff,   g_ff);
    cudaGetSymbolAddress((void**)&proj, g_proj);
    cudaGetSymbolAddress((void**)&mean, g_mean);
    cudaGetSymbolAddress((void**)&stdv, g_std);
    cudaGetSymbolAddress((void**)&rstd, g_rstd);
    cudaGetSymbolAddress((void**)&wemb,  g_wemb);
    cudaGetSymbolAddress((void**)&wq_t,  g_wq_t);
    cudaGetSymbolAddress((void**)&wk_t,  g_wk_t);
    cudaGetSymbolAddress((void**)&wv_t,  g_wv_t);
    cudaGetSymbolAddress((void**)&wo_t,  g_wo_t);
    cudaGetSymbolAddress((void**)&wff1,  g_wff1);
    cudaGetSymbolAddress((void**)&wff2,  g_wff2);
    cudaGetSymbolAddress((void**)&wproj, g_wproj);

    // weight convert + transpose to half [Dout][K]
    dim3 thr(32, 8);
    cvt_w_kernel<<<dim3(TKP / 32, DMOD / 32), thr>>>(emb_W, wemb, TT, DMOD, TKP, DMOD);
    for (int l = 0; l < LAYERS; l++) {
        size_t o = (size_t)l * DMOD * DMOD;
        cvt_w_kernel<<<dim3(DMOD / 32, DMOD / 32), thr>>>(Wq + o, wq_t + o, DMOD, DMOD, DMOD, DMOD);
        cvt_w_kernel<<<dim3(DMOD / 32, DMOD / 32), thr>>>(Wk + o, wk_t + o, DMOD, DMOD, DMOD, DMOD);
        cvt_w_kernel<<<dim3(DMOD / 32, DMOD / 32), thr>>>(Wv + o, wv_t + o, DMOD, DMOD, DMOD, DMOD);
        cvt_w_kernel<<<dim3(DMOD / 32, DMOD / 32), thr>>>(Wo + o, wo_t + o, DMOD, DMOD, DMOD, DMOD);
        size_t of = (size_t)l * DMOD * FFD;
        cvt_w_kernel<<<dim3(DMOD / 32, FFD / 32), thr>>>(ff1_W + of, wff1 + of, DMOD, FFD, DMOD, FFD);
        cvt_w_kernel<<<dim3(FFD / 32, DMOD / 32), thr>>>(ff2_W + of, wff2 + of, FFD, DMOD, FFD, DMOD);
    }
    cvt_w_kernel<<<dim3(DMOD / 32, PRJP / 32), thr>>>(proj_W, wproj, DMOD, PRED, DMOD, PRJP);

    revin_stats_kernel<<<dim3((CC + 127) / 128, BB), 128>>>(x_enc, mean, stdv, rstd);
    {
        dim3 grid((TT + 31) / 32, (LTOK + 31) / 32, BB);
        build_tok_kernel<<<grid, thr>>>(x_enc, x_mark, mean, rstd, revin_w, revin_b, tok);
    }
    // embedding: fp32 residual + half copy
    launch_gemm(tok, wemb, emb_b, x, xt, NROW, TKP, DMOD, 0);

    for (int l = 0; l < LAYERS; l++) {
        size_t o = (size_t)l * DMOD * DMOD;
        launch_gemm(xt, wq_t + o, bq + l * DMOD, q, nullptr, NROW, DMOD, DMOD, 1);
        launch_gemm(xt, wk_t + o, bk + l * DMOD, k, nullptr, NROW, DMOD, DMOD, 1);
        launch_gemm(xt, wv_t + o, bv + l * DMOD, v, nullptr, NROW, DMOD, DMOD, 0);
        attn_kernel<<<BB * HH, 512>>>(q, k, v, a);
        launch_gemm(a, wo_t + o, bo + l * DMOD, tmp, nullptr, NROW, DMOD, DMOD, 0);
        add_ln_kernel<<<NROW, 256>>>(x, tmp, ln1_w + l * DMOD, ln1_b + l * DMOD, xt, 1);
        size_t of = (size_t)l * DMOD * FFD;
        launch_gemm(xt, wff1 + of, ff1_b + l * FFD, nullptr, ff, NROW, DMOD, FFD, 2);
        launch_gemm(ff, wff2 + of, ff2_b + l * DMOD, tmp, nullptr, NROW, FFD, DMOD, 0);
        add_ln_kernel<<<NROW, 256>>>(x, tmp, ln2_w + l * DMOD, ln2_b + l * DMOD, xt, 1);
    }
    add_ln_kernel<<<NROW, 256>>>(x, nullptr, lnf_w, lnf_b, xt, 0);
    launch_gemm(xt, wproj, proj_b, proj, nullptr, NROW, DMOD, PRED, 0);
    {
        dim3 grid((CC + 31) / 32, (PRED + 31) / 32, BB);
        out_kernel<<<grid, thr>>>(proj, revin_w, revin_b, mean, stdv, (float*)d_out);
    }
}